// round 1
// baseline (speedup 1.0000x reference)
#include <cuda_runtime.h>
#include <cstdint>

#define Hdim 256
#define Sdim 512
#define Bdim 4
#define NROWS (Bdim * Sdim)   // 2048

// scratch: projected h (with b_h folded) and h'
__device__ float g_ht[NROWS * Hdim];
__device__ float g_htp[NROWS * Hdim];

__device__ __forceinline__ float fast_tanh(float x) {
    float y;
    asm("tanh.approx.f32 %0, %1;" : "=f"(y) : "f"(x));
    return y;
}

// ---------------------------------------------------------------------------
// Kernel A: ht = h @ W_t + b_h ; htp = h @ W_t'  (flat GEMM 2048x256 @ 256x256 x2)
// Block: 256 threads, 16 rows per block. Thread k computes column k for 16 rows.
// ---------------------------------------------------------------------------
#define KA_ROWS 16

__global__ __launch_bounds__(256, 2)
void proj_kernel(const float* __restrict__ h,
                 const float* __restrict__ Wt,
                 const float* __restrict__ Wtp,
                 const float* __restrict__ bh)
{
    __shared__ __align__(16) float sHT[Hdim][20];  // transposed [h][row], padded
    const int row0 = blockIdx.x * KA_ROWS;
    const int tid = threadIdx.x;

    // stage 16 h rows, transposed
    const float4* h4 = reinterpret_cast<const float4*>(h + (size_t)row0 * Hdim);
#pragma unroll
    for (int i = 0; i < 4; i++) {
        int idx = tid + i * 256;       // f4 index over 16x64
        int r = idx >> 6;
        int c4 = idx & 63;
        float4 v = h4[idx];
        int c = c4 * 4;
        sHT[c + 0][r] = v.x;
        sHT[c + 1][r] = v.y;
        sHT[c + 2][r] = v.z;
        sHT[c + 3][r] = v.w;
    }
    __syncthreads();

    const int k = tid;
    float accT[KA_ROWS], accP[KA_ROWS];
#pragma unroll
    for (int r = 0; r < KA_ROWS; r++) { accT[r] = 0.f; accP[r] = 0.f; }

#pragma unroll 2
    for (int hh = 0; hh < Hdim; hh++) {
        float wt = __ldg(&Wt[hh * Hdim + k]);
        float wp = __ldg(&Wtp[hh * Hdim + k]);
        const float4* hv4 = reinterpret_cast<const float4*>(&sHT[hh][0]);
        float4 v0 = hv4[0], v1 = hv4[1], v2 = hv4[2], v3 = hv4[3];
        float hv[16] = { v0.x, v0.y, v0.z, v0.w,
                         v1.x, v1.y, v1.z, v1.w,
                         v2.x, v2.y, v2.z, v2.w,
                         v3.x, v3.y, v3.z, v3.w };
#pragma unroll
        for (int r = 0; r < KA_ROWS; r++) {
            accT[r] = fmaf(hv[r], wt, accT[r]);
            accP[r] = fmaf(hv[r], wp, accP[r]);
        }
    }

    const float bhk = bh[k];
#pragma unroll
    for (int r = 0; r < KA_ROWS; r++) {
        g_ht [(size_t)(row0 + r) * Hdim + k] = accT[r] + bhk;
        g_htp[(size_t)(row0 + r) * Hdim + k] = accP[r];
    }
}

// ---------------------------------------------------------------------------
// Kernel B: fused scores + sigmoid + softmax + output GEMV.
// Block = (b, 4 consecutive t). 128 threads = 4 warps; warp w owns t = base+w.
// Lane l owns t' = tile*32 + l during score phase.
// ---------------------------------------------------------------------------
#define TT 4          // t rows per block (= warps per block)
#define TP 32         // t' rows per shared tile
#define NTILE (Sdim / TP)   // 16
#define TPAD 260      // smem row stride (floats): 260%32=4 -> conflict-free f4

__global__ __launch_bounds__(128, 4)
void attn_kernel(const float* __restrict__ h,
                 const float* __restrict__ Wa,
                 const float* __restrict__ ba_p,
                 float* __restrict__ out,
                 float* __restrict__ attn)
{
    __shared__ __align__(16) float sTile[TP][TPAD];     // 33280 B
    __shared__ __align__(16) float sScore[TT][Sdim];    //  8192 B
    __shared__ __align__(16) float sHt[TT][Hdim];       //  4096 B
    __shared__ __align__(16) float sWa[Hdim];           //  1024 B

    const int tid = threadIdx.x;
    const int w = tid >> 5;
    const int l = tid & 31;
    const int rowbase = blockIdx.x * TT;       // global (b*S + t)
    const int b = rowbase >> 9;                // /512

    // stage per-warp ht row + Wa
    {
        const float4* r4 = reinterpret_cast<const float4*>(g_ht + (size_t)(rowbase + w) * Hdim);
        reinterpret_cast<float4*>(sHt[w])[l]      = r4[l];
        reinterpret_cast<float4*>(sHt[w])[l + 32] = r4[l + 32];
        if (tid < 64)
            reinterpret_cast<float4*>(sWa)[tid] = reinterpret_cast<const float4*>(Wa)[tid];
    }
    __syncthreads();
    const float ba = ba_p[0];

    // ---- Phase 1: raw scores (tanh dot) ----
    const float* htp_b = g_htp + (size_t)b * Sdim * Hdim;
    for (int tile = 0; tile < NTILE; tile++) {
        __syncthreads();   // protect sTile reuse
        const float4* src = reinterpret_cast<const float4*>(htp_b + (size_t)tile * TP * Hdim);
#pragma unroll
        for (int i = 0; i < 16; i++) {
            int idx = tid + i * 128;          // f4 index over 32x64
            int r = idx >> 6;
            int c4 = idx & 63;
            *reinterpret_cast<float4*>(&sTile[r][c4 * 4]) = src[idx];
        }
        __syncthreads();

        const float4* prow = reinterpret_cast<const float4*>(&sTile[l][0]);
        const float4* hrow = reinterpret_cast<const float4*>(&sHt[w][0]);
        const float4* wrow = reinterpret_cast<const float4*>(sWa);
        float acc0 = 0.f, acc1 = 0.f;
#pragma unroll 8
        for (int g = 0; g < 64; g++) {
            float4 p = prow[g];
            float4 q = hrow[g];
            float4 a = wrow[g];
            acc0 = fmaf(a.x, fast_tanh(p.x + q.x), acc0);
            acc1 = fmaf(a.y, fast_tanh(p.y + q.y), acc1);
            acc0 = fmaf(a.z, fast_tanh(p.z + q.z), acc0);
            acc1 = fmaf(a.w, fast_tanh(p.w + q.w), acc1);
        }
        sScore[w][tile * TP + l] = acc0 + acc1;
    }
    __syncthreads();

    // ---- Phase 2: sigmoid + softmax (per warp over its own row) ----
    {
        float e[16];
        float sum = 0.f;
#pragma unroll
        for (int k2 = 0; k2 < 16; k2++) {
            float raw = sScore[w][k2 * 32 + l] + ba;
            float sg = 0.5f * fast_tanh(0.5f * raw) + 0.5f;   // sigmoid
            float ev = __expf(sg);
            e[k2] = ev;
            sum += ev;
        }
#pragma unroll
        for (int off = 16; off; off >>= 1)
            sum += __shfl_xor_sync(0xFFFFFFFFu, sum, off);
        float inv = __fdividef(1.0f, sum);
#pragma unroll
        for (int k2 = 0; k2 < 16; k2++)
            sScore[w][k2 * 32 + l] = e[k2] * inv;
        __syncwarp();
        // vectorized writeout of attention weights
        const float4* srow = reinterpret_cast<const float4*>(&sScore[w][0]);
        float4* attn4 = reinterpret_cast<float4*>(attn + (size_t)(rowbase + w) * Sdim);
#pragma unroll
        for (int k2 = 0; k2 < 4; k2++)
            attn4[k2 * 32 + l] = srow[k2 * 32 + l];
    }

    // ---- Phase 3: output[b,t,:] = sum_t' w[t'] * h[b,t',:] ----
    float o0x = 0.f, o0y = 0.f, o0z = 0.f, o0w = 0.f;
    float o1x = 0.f, o1y = 0.f, o1z = 0.f, o1w = 0.f;
    const float* h_b = h + (size_t)b * Sdim * Hdim;
    for (int tile = 0; tile < NTILE; tile++) {
        __syncthreads();
        const float4* src = reinterpret_cast<const float4*>(h_b + (size_t)tile * TP * Hdim);
#pragma unroll
        for (int i = 0; i < 16; i++) {
            int idx = tid + i * 128;
            int r = idx >> 6;
            int c4 = idx & 63;
            *reinterpret_cast<float4*>(&sTile[r][c4 * 4]) = src[idx];
        }
        __syncthreads();
#pragma unroll 4
        for (int tp = 0; tp < TP; tp++) {
            float wv = sScore[w][tile * TP + tp];
            float4 v0 = *reinterpret_cast<const float4*>(&sTile[tp][4 * l]);
            float4 v1 = *reinterpret_cast<const float4*>(&sTile[tp][128 + 4 * l]);
            o0x = fmaf(wv, v0.x, o0x);  o0y = fmaf(wv, v0.y, o0y);
            o0z = fmaf(wv, v0.z, o0z);  o0w = fmaf(wv, v0.w, o0w);
            o1x = fmaf(wv, v1.x, o1x);  o1y = fmaf(wv, v1.y, o1y);
            o1z = fmaf(wv, v1.z, o1z);  o1w = fmaf(wv, v1.w, o1w);
        }
    }
    float* orow = out + (size_t)(rowbase + w) * Hdim;
    reinterpret_cast<float4*>(orow)[l]      = make_float4(o0x, o0y, o0z, o0w);
    reinterpret_cast<float4*>(orow)[32 + l] = make_float4(o1x, o1y, o1z, o1w);
}

// ---------------------------------------------------------------------------
extern "C" void kernel_launch(void* const* d_in, const int* in_sizes, int n_in,
                              void* d_out, int out_size)
{
    const float* h   = (const float*)d_in[0];
    const float* Wt  = (const float*)d_in[1];
    const float* Wtp = (const float*)d_in[2];
    const float* bh  = (const float*)d_in[3];
    const float* Wa  = (const float*)d_in[4];
    const float* ba  = (const float*)d_in[5];

    float* out  = (float*)d_out;                  // [B,S,H] = 524288
    float* attn = out + (size_t)NROWS * Hdim;     // [B,S,S] = 1048576

    proj_kernel<<<NROWS / KA_ROWS, 256>>>(h, Wt, Wtp, bh);
    attn_kernel<<<NROWS / TT, 128>>>(h, Wa, ba, out, attn);
}

// round 2
// speedup vs baseline: 1.1372x; 1.1372x over previous
#include <cuda_runtime.h>
#include <cstdint>

#define Hdim 256
#define Sdim 512
#define Bdim 4
#define NROWS (Bdim * Sdim)   // 2048

// scratch: projected h (with b_h folded) and h'
__device__ float g_ht[NROWS * Hdim];
__device__ float g_htp[NROWS * Hdim];

__device__ __forceinline__ float fast_tanh(float x) {
    float y;
    asm("tanh.approx.f32 %0, %1;" : "=f"(y) : "f"(x));
    return y;
}

// ---------------------------------------------------------------------------
// Kernel A: ht = h @ W_t + b_h ; htp = h @ W_t'
// ---------------------------------------------------------------------------
#define KA_ROWS 16

__global__ __launch_bounds__(256, 2)
void proj_kernel(const float* __restrict__ h,
                 const float* __restrict__ Wt,
                 const float* __restrict__ Wtp,
                 const float* __restrict__ bh)
{
    __shared__ __align__(16) float sHT[Hdim][20];  // transposed [h][row], padded
    const int row0 = blockIdx.x * KA_ROWS;
    const int tid = threadIdx.x;

    const float4* h4 = reinterpret_cast<const float4*>(h + (size_t)row0 * Hdim);
#pragma unroll
    for (int i = 0; i < 4; i++) {
        int idx = tid + i * 256;       // f4 index over 16x64
        int r = idx >> 6;
        int c4 = idx & 63;
        float4 v = h4[idx];
        int c = c4 * 4;
        sHT[c + 0][r] = v.x;
        sHT[c + 1][r] = v.y;
        sHT[c + 2][r] = v.z;
        sHT[c + 3][r] = v.w;
    }
    __syncthreads();

    const int k = tid;
    float accT[KA_ROWS], accP[KA_ROWS];
#pragma unroll
    for (int r = 0; r < KA_ROWS; r++) { accT[r] = 0.f; accP[r] = 0.f; }

#pragma unroll 4
    for (int hh = 0; hh < Hdim; hh++) {
        float wt = __ldg(&Wt[hh * Hdim + k]);
        float wp = __ldg(&Wtp[hh * Hdim + k]);
        const float4* hv4 = reinterpret_cast<const float4*>(&sHT[hh][0]);
        float4 v0 = hv4[0], v1 = hv4[1], v2 = hv4[2], v3 = hv4[3];
        float hv[16] = { v0.x, v0.y, v0.z, v0.w,
                         v1.x, v1.y, v1.z, v1.w,
                         v2.x, v2.y, v2.z, v2.w,
                         v3.x, v3.y, v3.z, v3.w };
#pragma unroll
        for (int r = 0; r < KA_ROWS; r++) {
            accT[r] = fmaf(hv[r], wt, accT[r]);
            accP[r] = fmaf(hv[r], wp, accP[r]);
        }
    }

    const float bhk = bh[k];
#pragma unroll
    for (int r = 0; r < KA_ROWS; r++) {
        g_ht [(size_t)(row0 + r) * Hdim + k] = accT[r] + bhk;
        g_htp[(size_t)(row0 + r) * Hdim + k] = accP[r];
    }
}

// ---------------------------------------------------------------------------
// Kernel B: fused scores + sigmoid + softmax + output GEMV.
// Block = 4 t-rows, 128 threads = 4 warps; warp w owns t = base+w.
// Tiles of TP=16 t'-rows, double-buffered via cp.async.
// Lanes 0-15: t' = l, k in [0,128). Lanes 16-31: t' = l-16, k in [128,256).
// ---------------------------------------------------------------------------
#define TT 4
#define TP 16
#define NTILE (Sdim / TP)   // 32
#define TPAD 260            // 260 % 32 == 4 -> conflict-free f4 column reads

__global__ __launch_bounds__(128, 4)
void attn_kernel(const float* __restrict__ h,
                 const float* __restrict__ Wa,
                 const float* __restrict__ ba_p,
                 float* __restrict__ out,
                 float* __restrict__ attn)
{
    __shared__ __align__(16) float sTile[2][TP][TPAD];  // 33280 B
    __shared__ __align__(16) float sScore[TT][Sdim];    //  8192 B
    __shared__ __align__(16) float sHt[TT][Hdim];       //  4096 B
    __shared__ __align__(16) float sWa[Hdim];           //  1024 B

    const int tid = threadIdx.x;
    const int w = tid >> 5;
    const int l = tid & 31;
    const int rowbase = blockIdx.x * TT;       // global (b*S + t)
    const int b = rowbase >> 9;                // /512

    const float* htp_b = g_htp + (size_t)b * Sdim * Hdim;
    const float* h_b   = h     + (size_t)b * Sdim * Hdim;

    // async stage of one 16x256 tile (1024 float4) by 128 threads
    auto stage = [&](int buf, const float* srcBase) {
        const float4* src = reinterpret_cast<const float4*>(srcBase);
#pragma unroll
        for (int i = 0; i < 8; i++) {
            int idx = tid + i * 128;
            int r = idx >> 6;
            int c4 = idx & 63;
            uint32_t d = (uint32_t)__cvta_generic_to_shared(&sTile[buf][r][c4 * 4]);
            asm volatile("cp.async.cg.shared.global [%0], [%1], 16;\n"
                         :: "r"(d), "l"(src + idx));
        }
        asm volatile("cp.async.commit_group;\n");
    };

    // prefetch first score tile immediately
    stage(0, htp_b);

    // stage per-warp ht row + Wa (regular loads; covered by first barrier)
    {
        const float4* r4 = reinterpret_cast<const float4*>(g_ht + (size_t)(rowbase + w) * Hdim);
        reinterpret_cast<float4*>(sHt[w])[l]      = r4[l];
        reinterpret_cast<float4*>(sHt[w])[l + 32] = r4[l + 32];
        if (tid < 64)
            reinterpret_cast<float4*>(sWa)[tid] = reinterpret_cast<const float4*>(Wa)[tid];
    }
    const float ba = ba_p[0];

    const int tpl = l & 15;
    const int kh  = l >> 4;         // 0: k[0,128), 1: k[128,256)

    // ---- Phase 1: raw scores (tanh dot), double-buffered ----
    for (int tile = 0; tile < NTILE; tile++) {
        const int buf = tile & 1;
        if (tile + 1 < NTILE) {
            stage(buf ^ 1, htp_b + (size_t)(tile + 1) * TP * Hdim);
            asm volatile("cp.async.wait_group 1;\n");
        } else {
            asm volatile("cp.async.wait_group 0;\n");
        }
        __syncthreads();

        const float4* prow = reinterpret_cast<const float4*>(&sTile[buf][tpl][kh * 128]);
        const float4* qrow = reinterpret_cast<const float4*>(&sHt[w][kh * 128]);
        const float4* arow = reinterpret_cast<const float4*>(&sWa[kh * 128]);
        float acc0 = 0.f, acc1 = 0.f;
#pragma unroll 8
        for (int g = 0; g < 32; g++) {
            float4 p = prow[g];
            float4 q = qrow[g];
            float4 a = arow[g];
            acc0 = fmaf(a.x, fast_tanh(p.x + q.x), acc0);
            acc1 = fmaf(a.y, fast_tanh(p.y + q.y), acc1);
            acc0 = fmaf(a.z, fast_tanh(p.z + q.z), acc0);
            acc1 = fmaf(a.w, fast_tanh(p.w + q.w), acc1);
        }
        float s = acc0 + acc1;
        s += __shfl_xor_sync(0xFFFFFFFFu, s, 16);
        if (l < 16) sScore[w][tile * TP + l] = s;
        __syncthreads();
    }

    // prefetch first output tile NOW; latency hides under softmax
    stage(0, h_b);

    // ---- Phase 2: sigmoid + softmax (per warp over its own row) ----
    {
        float e[16];
        float sum = 0.f;
#pragma unroll
        for (int k2 = 0; k2 < 16; k2++) {
            float raw = sScore[w][k2 * 32 + l] + ba;
            float sg = 0.5f * fast_tanh(0.5f * raw) + 0.5f;   // sigmoid
            float ev = __expf(sg);
            e[k2] = ev;
            sum += ev;
        }
#pragma unroll
        for (int off = 16; off; off >>= 1)
            sum += __shfl_xor_sync(0xFFFFFFFFu, sum, off);
        float inv = __fdividef(1.0f, sum);
#pragma unroll
        for (int k2 = 0; k2 < 16; k2++)
            sScore[w][k2 * 32 + l] = e[k2] * inv;
        __syncwarp();
        // vectorized writeout of attention weights
        const float4* srow = reinterpret_cast<const float4*>(&sScore[w][0]);
        float4* attn4 = reinterpret_cast<float4*>(attn + (size_t)(rowbase + w) * Sdim);
#pragma unroll
        for (int k2 = 0; k2 < 4; k2++)
            attn4[k2 * 32 + l] = srow[k2 * 32 + l];
    }

    // ---- Phase 3: output[b,t,:] = sum_t' w[t'] * h[b,t',:], double-buffered ----
    float o0x = 0.f, o0y = 0.f, o0z = 0.f, o0w = 0.f;
    float o1x = 0.f, o1y = 0.f, o1z = 0.f, o1w = 0.f;
    for (int tile = 0; tile < NTILE; tile++) {
        const int buf = tile & 1;
        if (tile + 1 < NTILE) {
            stage(buf ^ 1, h_b + (size_t)(tile + 1) * TP * Hdim);
            asm volatile("cp.async.wait_group 1;\n");
        } else {
            asm volatile("cp.async.wait_group 0;\n");
        }
        __syncthreads();

#pragma unroll 8
        for (int tp = 0; tp < TP; tp++) {
            float wv = sScore[w][tile * TP + tp];
            float4 v0 = *reinterpret_cast<const float4*>(&sTile[buf][tp][4 * l]);
            float4 v1 = *reinterpret_cast<const float4*>(&sTile[buf][tp][128 + 4 * l]);
            o0x = fmaf(wv, v0.x, o0x);  o0y = fmaf(wv, v0.y, o0y);
            o0z = fmaf(wv, v0.z, o0z);  o0w = fmaf(wv, v0.w, o0w);
            o1x = fmaf(wv, v1.x, o1x);  o1y = fmaf(wv, v1.y, o1y);
            o1z = fmaf(wv, v1.z, o1z);  o1w = fmaf(wv, v1.w, o1w);
        }
        __syncthreads();
    }
    float* orow = out + (size_t)(rowbase + w) * Hdim;
    reinterpret_cast<float4*>(orow)[l]      = make_float4(o0x, o0y, o0z, o0w);
    reinterpret_cast<float4*>(orow)[32 + l] = make_float4(o1x, o1y, o1z, o1w);
}

// ---------------------------------------------------------------------------
extern "C" void kernel_launch(void* const* d_in, const int* in_sizes, int n_in,
                              void* d_out, int out_size)
{
    const float* h   = (const float*)d_in[0];
    const float* Wt  = (const float*)d_in[1];
    const float* Wtp = (const float*)d_in[2];
    const float* bh  = (const float*)d_in[3];
    const float* Wa  = (const float*)d_in[4];
    const float* ba  = (const float*)d_in[5];

    float* out  = (float*)d_out;                  // [B,S,H] = 524288
    float* attn = out + (size_t)NROWS * Hdim;     // [B,S,S] = 1048576

    proj_kernel<<<NROWS / KA_ROWS, 256>>>(h, Wt, Wtp, bh);
    attn_kernel<<<NROWS / TT, 128>>>(h, Wa, ba, out, attn);
}

// round 3
// speedup vs baseline: 1.3202x; 1.1609x over previous
#include <cuda_runtime.h>
#include <cstdint>

#define Hdim 256
#define Sdim 512
#define Bdim 4
#define NROWS (Bdim * Sdim)   // 2048

// scratch: projected h (with b_h folded) and h'
__device__ float g_ht[NROWS * Hdim];
__device__ float g_htp[NROWS * Hdim];

__device__ __forceinline__ float fast_tanh(float x) {
    float y;
    asm("tanh.approx.f32 %0, %1;" : "=f"(y) : "f"(x));
    return y;
}

// ---------------------------------------------------------------------------
// Kernel A: ht = h @ W_t + b_h ; htp = h @ W_t'
// ---------------------------------------------------------------------------
#define KA_ROWS 16

__global__ __launch_bounds__(256, 2)
void proj_kernel(const float* __restrict__ h,
                 const float* __restrict__ Wt,
                 const float* __restrict__ Wtp,
                 const float* __restrict__ bh)
{
    __shared__ __align__(16) float sHT[Hdim][20];  // transposed [h][row], padded
    const int row0 = blockIdx.x * KA_ROWS;
    const int tid = threadIdx.x;

    const float4* h4 = reinterpret_cast<const float4*>(h + (size_t)row0 * Hdim);
#pragma unroll
    for (int i = 0; i < 4; i++) {
        int idx = tid + i * 256;       // f4 index over 16x64
        int r = idx >> 6;
        int c4 = idx & 63;
        float4 v = h4[idx];
        int c = c4 * 4;
        sHT[c + 0][r] = v.x;
        sHT[c + 1][r] = v.y;
        sHT[c + 2][r] = v.z;
        sHT[c + 3][r] = v.w;
    }
    __syncthreads();

    const int k = tid;
    float accT[KA_ROWS], accP[KA_ROWS];
#pragma unroll
    for (int r = 0; r < KA_ROWS; r++) { accT[r] = 0.f; accP[r] = 0.f; }

#pragma unroll 4
    for (int hh = 0; hh < Hdim; hh++) {
        float wt = __ldg(&Wt[hh * Hdim + k]);
        float wp = __ldg(&Wtp[hh * Hdim + k]);
        const float4* hv4 = reinterpret_cast<const float4*>(&sHT[hh][0]);
        float4 v0 = hv4[0], v1 = hv4[1], v2 = hv4[2], v3 = hv4[3];
        float hv[16] = { v0.x, v0.y, v0.z, v0.w,
                         v1.x, v1.y, v1.z, v1.w,
                         v2.x, v2.y, v2.z, v2.w,
                         v3.x, v3.y, v3.z, v3.w };
#pragma unroll
        for (int r = 0; r < KA_ROWS; r++) {
            accT[r] = fmaf(hv[r], wt, accT[r]);
            accP[r] = fmaf(hv[r], wp, accP[r]);
        }
    }

    const float bhk = bh[k];
#pragma unroll
    for (int r = 0; r < KA_ROWS; r++) {
        g_ht [(size_t)(row0 + r) * Hdim + k] = accT[r] + bhk;
        g_htp[(size_t)(row0 + r) * Hdim + k] = accP[r];
    }
}

// ---------------------------------------------------------------------------
// Kernel B: fused scores + sigmoid + softmax + output GEMV.
// Block = 4 t-rows, 128 threads = 4 warps; warp w owns t = base+w.
// Phase 1: tile of 16 t' rows; lane l: r=l>>3 owns rows {r,r+4,r+8,r+12},
//          kq=l&7 owns f4 columns {kq+8g} -> 6 LDS per 16 tanh, conflict-free.
// Phase 3: thread owns one f4 column for ALL 4 t rows, half the tile rows.
// ---------------------------------------------------------------------------
#define TT 4
#define TP 16
#define NTILE (Sdim / TP)   // 32
#define TPAD 260            // 260 % 32 == 4

__global__ __launch_bounds__(128, 4)
void attn_kernel(const float* __restrict__ h,
                 const float* __restrict__ Wa,
                 const float* __restrict__ ba_p,
                 float* __restrict__ out,
                 float* __restrict__ attn)
{
    __shared__ __align__(16) float sTile[2][TP][TPAD];  // 33280 B
    __shared__ __align__(16) float sScore[TT][Sdim];    //  8192 B
    __shared__ __align__(16) float sHt[TT][Hdim];       //  4096 B
    __shared__ __align__(16) float sWa[Hdim];           //  1024 B

    const int tid = threadIdx.x;
    const int w = tid >> 5;
    const int l = tid & 31;
    const int rowbase = blockIdx.x * TT;       // global (b*S + t)
    const int b = rowbase >> 9;                // /512

    const float* htp_b = g_htp + (size_t)b * Sdim * Hdim;
    const float* h_b   = h     + (size_t)b * Sdim * Hdim;

    // async stage of one 16x256 tile (1024 float4) by 128 threads
    auto stage = [&](int buf, const float* srcBase) {
        const float4* src = reinterpret_cast<const float4*>(srcBase);
#pragma unroll
        for (int i = 0; i < 8; i++) {
            int idx = tid + i * 128;
            int r = idx >> 6;
            int c4 = idx & 63;
            uint32_t d = (uint32_t)__cvta_generic_to_shared(&sTile[buf][r][c4 * 4]);
            asm volatile("cp.async.cg.shared.global [%0], [%1], 16;\n"
                         :: "r"(d), "l"(src + idx));
        }
        asm volatile("cp.async.commit_group;\n");
    };

    // prefetch first score tile immediately
    stage(0, htp_b);

    // stage per-warp ht row + Wa
    {
        const float4* r4 = reinterpret_cast<const float4*>(g_ht + (size_t)(rowbase + w) * Hdim);
        reinterpret_cast<float4*>(sHt[w])[l]      = r4[l];
        reinterpret_cast<float4*>(sHt[w])[l + 32] = r4[l + 32];
        if (tid < 64)
            reinterpret_cast<float4*>(sWa)[tid] = reinterpret_cast<const float4*>(Wa)[tid];
    }
    const float ba = ba_p[0];

    const int r  = l >> 3;   // row group: rows {r, r+4, r+8, r+12}
    const int kq = l & 7;    // k-slice: f4 indices {kq + 8g}

    // ---- Phase 1: raw scores (tanh dot), R=4 rows per lane ----
    for (int tile = 0; tile < NTILE; tile++) {
        const int buf = tile & 1;
        if (tile + 1 < NTILE) {
            stage(buf ^ 1, htp_b + (size_t)(tile + 1) * TP * Hdim);
            asm volatile("cp.async.wait_group 1;\n");
        } else {
            asm volatile("cp.async.wait_group 0;\n");
        }
        __syncthreads();

        float acc0 = 0.f, acc1 = 0.f, acc2 = 0.f, acc3 = 0.f;
#pragma unroll
        for (int g = 0; g < 8; g++) {
            const int f4i = kq + 8 * g;
            float4 q = *reinterpret_cast<const float4*>(&sHt[w][f4i * 4]);
            float4 a = *reinterpret_cast<const float4*>(&sWa[f4i * 4]);
            float4 p0 = *reinterpret_cast<const float4*>(&sTile[buf][r     ][f4i * 4]);
            float4 p1 = *reinterpret_cast<const float4*>(&sTile[buf][r + 4 ][f4i * 4]);
            float4 p2 = *reinterpret_cast<const float4*>(&sTile[buf][r + 8 ][f4i * 4]);
            float4 p3 = *reinterpret_cast<const float4*>(&sTile[buf][r + 12][f4i * 4]);
            acc0 = fmaf(a.x, fast_tanh(p0.x + q.x), acc0);
            acc0 = fmaf(a.y, fast_tanh(p0.y + q.y), acc0);
            acc0 = fmaf(a.z, fast_tanh(p0.z + q.z), acc0);
            acc0 = fmaf(a.w, fast_tanh(p0.w + q.w), acc0);
            acc1 = fmaf(a.x, fast_tanh(p1.x + q.x), acc1);
            acc1 = fmaf(a.y, fast_tanh(p1.y + q.y), acc1);
            acc1 = fmaf(a.z, fast_tanh(p1.z + q.z), acc1);
            acc1 = fmaf(a.w, fast_tanh(p1.w + q.w), acc1);
            acc2 = fmaf(a.x, fast_tanh(p2.x + q.x), acc2);
            acc2 = fmaf(a.y, fast_tanh(p2.y + q.y), acc2);
            acc2 = fmaf(a.z, fast_tanh(p2.z + q.z), acc2);
            acc2 = fmaf(a.w, fast_tanh(p2.w + q.w), acc2);
            acc3 = fmaf(a.x, fast_tanh(p3.x + q.x), acc3);
            acc3 = fmaf(a.y, fast_tanh(p3.y + q.y), acc3);
            acc3 = fmaf(a.z, fast_tanh(p3.z + q.z), acc3);
            acc3 = fmaf(a.w, fast_tanh(p3.w + q.w), acc3);
        }
        // reduce across the 8 k-slices (lanes sharing r)
#pragma unroll
        for (int off = 1; off < 8; off <<= 1) {
            acc0 += __shfl_xor_sync(0xFFFFFFFFu, acc0, off);
            acc1 += __shfl_xor_sync(0xFFFFFFFFu, acc1, off);
            acc2 += __shfl_xor_sync(0xFFFFFFFFu, acc2, off);
            acc3 += __shfl_xor_sync(0xFFFFFFFFu, acc3, off);
        }
        if (kq == 0) {
            sScore[w][tile * TP + r     ] = acc0;
            sScore[w][tile * TP + r + 4 ] = acc1;
            sScore[w][tile * TP + r + 8 ] = acc2;
            sScore[w][tile * TP + r + 12] = acc3;
        }
        __syncthreads();
    }

    // prefetch first output tile NOW; latency hides under softmax
    stage(0, h_b);

    // ---- Phase 2: sigmoid + softmax (per warp over its own row) ----
    {
        float e[16];
        float sum = 0.f;
#pragma unroll
        for (int k2 = 0; k2 < 16; k2++) {
            float raw = sScore[w][k2 * 32 + l] + ba;
            float sg = 0.5f * fast_tanh(0.5f * raw) + 0.5f;   // sigmoid
            float ev = __expf(sg);
            e[k2] = ev;
            sum += ev;
        }
#pragma unroll
        for (int off = 16; off; off >>= 1)
            sum += __shfl_xor_sync(0xFFFFFFFFu, sum, off);
        float inv = __fdividef(1.0f, sum);
#pragma unroll
        for (int k2 = 0; k2 < 16; k2++)
            sScore[w][k2 * 32 + l] = e[k2] * inv;
        __syncwarp();
        const float4* srow = reinterpret_cast<const float4*>(&sScore[w][0]);
        float4* attn4 = reinterpret_cast<float4*>(attn + (size_t)(rowbase + w) * Sdim);
#pragma unroll
        for (int k2 = 0; k2 < 4; k2++)
            attn4[k2 * 32 + l] = srow[k2 * 32 + l];
    }

    // ---- Phase 3: output[b,t,:] for ALL 4 t per thread ----
    // thread owns f4 column c = l + 32*(w&1); warps {0,1}: tile rows 0-7,
    // warps {2,3}: tile rows 8-15. Halves combined at the end.
    const int c    = l + 32 * (w & 1);   // f4 column 0..63
    const int half = w >> 1;             // 0 or 1
    float4 acc[TT];
#pragma unroll
    for (int t = 0; t < TT; t++) acc[t] = make_float4(0.f, 0.f, 0.f, 0.f);

    for (int tile = 0; tile < NTILE; tile++) {
        const int buf = tile & 1;
        if (tile + 1 < NTILE) {
            stage(buf ^ 1, h_b + (size_t)(tile + 1) * TP * Hdim);
            asm volatile("cp.async.wait_group 1;\n");
        } else {
            asm volatile("cp.async.wait_group 0;\n");
        }
        __syncthreads();

        // hoist the 8 scores per t row (warp-uniform broadcast loads)
        const int tb = tile * TP + half * 8;
        float s[TT][8];
#pragma unroll
        for (int t = 0; t < TT; t++) {
            float4 x = *reinterpret_cast<const float4*>(&sScore[t][tb]);
            float4 y = *reinterpret_cast<const float4*>(&sScore[t][tb + 4]);
            s[t][0] = x.x; s[t][1] = x.y; s[t][2] = x.z; s[t][3] = x.w;
            s[t][4] = y.x; s[t][5] = y.y; s[t][6] = y.z; s[t][7] = y.w;
        }
#pragma unroll
        for (int tp = 0; tp < 8; tp++) {
            float4 v = *reinterpret_cast<const float4*>(&sTile[buf][half * 8 + tp][c * 4]);
#pragma unroll
            for (int t = 0; t < TT; t++) {
                acc[t].x = fmaf(s[t][tp], v.x, acc[t].x);
                acc[t].y = fmaf(s[t][tp], v.y, acc[t].y);
                acc[t].z = fmaf(s[t][tp], v.z, acc[t].z);
                acc[t].w = fmaf(s[t][tp], v.w, acc[t].w);
            }
        }
        __syncthreads();
    }

    // combine halves via spare sTile smem and write out
    float* scomb = &sTile[0][0][0];   // 4 t x 64 c float4 = 4 KB
    if (half == 1) {
#pragma unroll
        for (int t = 0; t < TT; t++)
            *reinterpret_cast<float4*>(&scomb[(t * 64 + c) * 4]) = acc[t];
    }
    __syncthreads();
    if (half == 0) {
#pragma unroll
        for (int t = 0; t < TT; t++) {
            float4 o = *reinterpret_cast<const float4*>(&scomb[(t * 64 + c) * 4]);
            o.x += acc[t].x; o.y += acc[t].y; o.z += acc[t].z; o.w += acc[t].w;
            *reinterpret_cast<float4*>(&out[(size_t)(rowbase + t) * Hdim + c * 4]) = o;
        }
    }
}

// ---------------------------------------------------------------------------
extern "C" void kernel_launch(void* const* d_in, const int* in_sizes, int n_in,
                              void* d_out, int out_size)
{
    const float* h   = (const float*)d_in[0];
    const float* Wt  = (const float*)d_in[1];
    const float* Wtp = (const float*)d_in[2];
    const float* bh  = (const float*)d_in[3];
    const float* Wa  = (const float*)d_in[4];
    const float* ba  = (const float*)d_in[5];

    float* out  = (float*)d_out;                  // [B,S,H] = 524288
    float* attn = out + (size_t)NROWS * Hdim;     // [B,S,S] = 1048576

    proj_kernel<<<NROWS / KA_ROWS, 256>>>(h, Wt, Wtp, bh);
    attn_kernel<<<NROWS / TT, 128>>>(h, Wa, ba, out, attn);
}